// round 6
// baseline (speedup 1.0000x reference)
#include <cuda_runtime.h>
#include <math.h>

#define N_STATE 131072
#define H 128

#define NBLOCKS 512
#define NTHREADS 256
#define COLS_PER_BLOCK 256                     // 64 float4 columns
#define C4_PER_BLOCK (COLS_PER_BLOCK / 4)      // 64

// Scratch + sync (allocation-free: __device__ globals; .bss -> zero at start)
__device__ float g_part[NBLOCKS * H];
__device__ float g_u[H];
__device__ unsigned g_count1;
__device__ unsigned g_count2;
__device__ volatile int g_flag;

// ---------------------------------------------------------------------------
// Fused persistent kernel. 512 blocks x 256 threads, all co-resident
// (64 regs, ~10KB smem -> 4 blocks/SM x 148 SMs = 592 >= 512: deadlock-free).
//
// Phase 1: block b: partial row-dots of W0 over its 256-col slab -> g_part.
// Barrier 1 (atomic count). Last block runs the serial chain:
//   V0=tanh(W0@xn+b0); fwd through W1,W2,W3 (tanh' diags); h=Wout.V+bout;
//   u = D0 W1^T D1 W2^T D2 W3^T Wout^T  -> g_u, release g_flag.
// Phase 3: block b: out[1+j] = (u . W0[:,j]) * 2/(xmax-xmin) on SAME slab
//   (L2-warm from phase 1). Last finisher resets counters for graph replay.
// ---------------------------------------------------------------------------
__global__ void __launch_bounds__(NTHREADS, 4) cbf_fused(
        const float* __restrict__ state,
        const float* __restrict__ xmax,
        const float* __restrict__ xmin,
        const float* __restrict__ W0,
        const float* __restrict__ b0v,
        const float* __restrict__ W1, const float* __restrict__ b1v,
        const float* __restrict__ W2, const float* __restrict__ b2v,
        const float* __restrict__ W3, const float* __restrict__ b3v,
        const float* __restrict__ Wout, const float* __restrict__ boutv,
        float* __restrict__ out) {
    __shared__ __align__(16) float xn_s[COLS_PER_BLOCK];
    __shared__ __align__(16) float4 part4[NTHREADS];
    __shared__ float v[H], nv[H], dd0[H], dd1[H], dd2[H], us[H], nus[H];
    __shared__ float psum[2 * H];
    __shared__ float red[4];
    __shared__ int is_last_s;

    const int tid = threadIdx.x;
    const int b = blockIdx.x;
    const int lane = tid & 31;
    const int warp = tid >> 5;                 // 0..7
    const float4* __restrict__ W4 = (const float4*)W0;
    const int rs4 = N_STATE / 4;

    // ---------------- Phase 1: row partial dots over this block's slab -----
    {
        const int c0 = b * COLS_PER_BLOCK;
        int j = c0 + tid;                      // NTHREADS == COLS_PER_BLOCK
        float mx = xmax[j], mn = xmin[j];
        xn_s[tid] = (2.0f * state[j] - (mx + mn)) / (mx - mn);
        __syncthreads();

        const int c04 = c0 / 4;
        const float4 x0 = ((const float4*)xn_s)[lane];
        const float4 x1 = ((const float4*)xn_s)[32 + lane];

        float acc[16];
        #pragma unroll
        for (int rr = 0; rr < 16; rr++) {
            const int r = warp * 16 + rr;
            float4 w = W4[r * rs4 + c04 + lane];
            acc[rr] = w.x * x0.x + w.y * x0.y + w.z * x0.z + w.w * x0.w;
        }
        #pragma unroll
        for (int rr = 0; rr < 16; rr++) {
            const int r = warp * 16 + rr;
            float4 w = W4[r * rs4 + c04 + 32 + lane];
            acc[rr] += w.x * x1.x + w.y * x1.y + w.z * x1.z + w.w * x1.w;
        }
        #pragma unroll
        for (int rr = 0; rr < 16; rr++) {
            float a = acc[rr];
            #pragma unroll
            for (int off = 16; off; off >>= 1)
                a += __shfl_down_sync(0xffffffffu, a, off);
            if (lane == 0) g_part[b * H + warp * 16 + rr] = a;
        }
    }

    // ---------------- Barrier 1: last-arriving block runs the chain --------
    if (tid == 0) {
        __threadfence();
        unsigned old = atomicAdd(&g_count1, 1u);
        is_last_s = (old == NBLOCKS - 1) ? 1 : 0;
    }
    __syncthreads();

    if (is_last_s) {
        // Phase A: reduce 512 partials per row (coalesced, 2-way split)
        {
            const int i = tid & (H - 1);
            const int g = tid >> 7;            // 0..1
            float s = 0.f;
            #pragma unroll 8
            for (int bb = g * 256; bb < (g + 1) * 256; bb++)
                s += g_part[bb * H + i];
            psum[g * H + i] = s;
        }
        __syncthreads();
        if (tid < H) {
            float s = psum[tid] + psum[H + tid] + b0v[tid];
            float a = tanhf(s);
            v[tid] = a;
            dd0[tid] = 1.f - a * a;
        }
        __syncthreads();

        // Forward chain: 8 warps x 16 rows each
        const float* Ws[3] = {W1, W2, W3};
        const float* bs[3] = {b1v, b2v, b3v};
        #pragma unroll
        for (int L = 0; L < 3; L++) {
            const float* __restrict__ W = Ws[L];
            const float* __restrict__ bb = bs[L];
            float acc[16];
            #pragma unroll
            for (int rr = 0; rr < 16; rr++) {
                const int r = warp * 16 + rr;
                float a = 0.f;
                #pragma unroll
                for (int k = 0; k < 4; k++)
                    a += W[r * H + k * 32 + lane] * v[k * 32 + lane];
                acc[rr] = a;
            }
            #pragma unroll
            for (int rr = 0; rr < 16; rr++) {
                float a = acc[rr];
                #pragma unroll
                for (int off = 16; off; off >>= 1)
                    a += __shfl_down_sync(0xffffffffu, a, off);
                if (lane == 0) nv[warp * 16 + rr] = a + bb[warp * 16 + rr];
            }
            __syncthreads();
            if (tid < H) {
                if (L == 0) { float a = tanhf(nv[tid]); v[tid] = a; dd1[tid] = 1.f - a * a; }
                else if (L == 1) { float a = tanhf(nv[tid]); v[tid] = a; dd2[tid] = 1.f - a * a; }
                else v[tid] = nv[tid];
            }
            __syncthreads();
        }

        // h = Wout . v + bout ; seed u = Wout
        if (tid < H) {
            float p = Wout[tid] * v[tid];
            #pragma unroll
            for (int off = 16; off; off >>= 1)
                p += __shfl_down_sync(0xffffffffu, p, off);
            if (lane == 0) red[warp] = p;      // warps 0..3
            us[tid] = Wout[tid];
        }
        __syncthreads();
        if (tid == 0) out[0] = red[0] + red[1] + red[2] + red[3] + boutv[0];
        __syncthreads();

        // Backward composition: 3 steps of outc[c] = dd[c] * sum_i W[i][c]*u[i]
        const float* Wb[3] = {W3, W2, W1};
        #pragma unroll
        for (int L = 0; L < 3; L++) {
            const float* __restrict__ W = Wb[L];
            const float* src = (L == 1) ? nus : us;
            const float* dd  = (L == 0) ? dd2 : (L == 1) ? dd1 : dd0;
            float* dst = (L == 1) ? us : nus;
            {
                const int c4 = tid & 31;
                const int ig = tid >> 5;       // 0..7 row groups of 16
                const float4* __restrict__ Wq = (const float4*)W;
                float4 a = make_float4(0.f, 0.f, 0.f, 0.f);
                #pragma unroll
                for (int k = 0; k < 16; k++) {
                    const int i = ig * 16 + k;
                    float4 w = Wq[i * (H / 4) + c4];
                    float ui = src[i];
                    a.x += ui * w.x; a.y += ui * w.y; a.z += ui * w.z; a.w += ui * w.w;
                }
                part4[tid] = a;
            }
            __syncthreads();
            if (tid < 32) {
                float4 s = make_float4(0.f, 0.f, 0.f, 0.f);
                #pragma unroll
                for (int g = 0; g < 8; g++) {
                    float4 p = part4[g * 32 + tid];
                    s.x += p.x; s.y += p.y; s.z += p.z; s.w += p.w;
                }
                const int c = tid * 4;
                dst[c + 0] = s.x * dd[c + 0];
                dst[c + 1] = s.y * dd[c + 1];
                dst[c + 2] = s.z * dd[c + 2];
                dst[c + 3] = s.w * dd[c + 3];
            }
            __syncthreads();
        }
        if (tid < H) g_u[tid] = nus[tid];
        __syncthreads();
        if (tid == 0) {
            __threadfence();
            g_flag = 1;                        // release
        }
    }

    // ---------------- Wait for u ------------------------------------------
    if (tid == 0) {
        while (g_flag == 0) __nanosleep(64);
    }
    __syncthreads();
    __threadfence();                            // acquire

    // ---------------- Phase 3: column dots on the SAME slab (L2-warm) ------
    {
        if (tid < H) us[tid] = g_u[tid];
        __syncthreads();

        const int c4l = tid & 63;               // 0..63 col4 within slab
        const int rg = tid >> 6;                // 0..3 row group of 32
        const int c4 = b * C4_PER_BLOCK + c4l;

        float4 a = make_float4(0.f, 0.f, 0.f, 0.f);
        #pragma unroll
        for (int k = 0; k < 32; k++) {
            const int i = rg * 32 + k;
            float4 w = W4[i * rs4 + c4];
            float ui = us[i];
            a.x += ui * w.x; a.y += ui * w.y; a.z += ui * w.z; a.w += ui * w.w;
        }
        part4[tid] = a;
        __syncthreads();

        if (tid < 64) {
            float4 s0 = part4[tid];
            float4 s1 = part4[64 + tid];
            float4 s2 = part4[128 + tid];
            float4 s3 = part4[192 + tid];
            float sx = s0.x + s1.x + s2.x + s3.x;
            float sy = s0.y + s1.y + s2.y + s3.y;
            float sz = s0.z + s1.z + s2.z + s3.z;
            float sw = s0.w + s1.w + s2.w + s3.w;
            const int c4g = b * C4_PER_BLOCK + tid;
            float4 mx = ((const float4*)xmax)[c4g];
            float4 mn = ((const float4*)xmin)[c4g];
            const int j = c4g * 4;
            out[1 + j + 0] = sx * 2.f / (mx.x - mn.x);
            out[1 + j + 1] = sy * 2.f / (mx.y - mn.y);
            out[1 + j + 2] = sz * 2.f / (mx.z - mn.z);
            out[1 + j + 3] = sw * 2.f / (mx.w - mn.w);
        }
    }

    // ---------------- Reset sync state for next graph replay ---------------
    if (tid == 0) {
        __threadfence();
        unsigned old = atomicAdd(&g_count2, 1u);
        if (old == NBLOCKS - 1) {
            g_count1 = 0u;
            g_count2 = 0u;
            g_flag = 0;
        }
    }
}

// ---------------------------------------------------------------------------
extern "C" void kernel_launch(void* const* d_in, const int* in_sizes, int n_in,
                              void* d_out, int out_size) {
    const float* state = (const float*)d_in[0];
    const float* xmax  = (const float*)d_in[1];
    const float* xmin  = (const float*)d_in[2];
    const float* W0    = (const float*)d_in[3];
    const float* b0    = (const float*)d_in[4];
    const float* W1    = (const float*)d_in[5];
    const float* b1    = (const float*)d_in[6];
    const float* W2    = (const float*)d_in[7];
    const float* b2    = (const float*)d_in[8];
    const float* W3    = (const float*)d_in[9];
    const float* b3    = (const float*)d_in[10];
    const float* Wout  = (const float*)d_in[11];
    const float* bout  = (const float*)d_in[12];
    float* out = (float*)d_out;

    cbf_fused<<<NBLOCKS, NTHREADS>>>(state, xmax, xmin, W0, b0,
                                     W1, b1, W2, b2, W3, b3, Wout, bout, out);
}